// round 12
// baseline (speedup 1.0000x reference)
#include <cuda_runtime.h>
#include <cstddef>

// ChebychevTransform: x[8,256,256,8] f32 -> out[8,256,256,128] f32
// out[b,h,w, c*16 + p*4 + k] = sum_{i,j} T[p,j]*T[k,i]*x[b,h+i-1,w+j-1,c]
// (zero pad: 1 before / 2 after, TF SAME n=4)
// T = [[1/6,1/3,1/3,1/6],[1/3,1/3,-1/3,-1/3],[1/3,-1/3,-1/3,1/3],[1/3,-2/3,2/3,-1/3]]
//
// Block = 256 threads = one (b, 8-row strip, 32 w-columns).
// Stage:   input halo tile (11 rows x 35 cols x 8 ch) into smem, transposed to
//          [t][c][wcol] with wcol stride padded to 36 -> conflict-free STS/LDS,
//          16B-aligned float4 reads. W-padding zeroed at staging time.
// Consume: warp = 4 adjacent columns (wl = wid*4); lane = (p=lane>>3, c=lane&7).
//          Per row t: two LDS.128 fetch words wl..wl+7 of (t,c); the 4 pixels'
//          tap windows are register slices of (A,B). 4-FMA dot with T[p,:],
//          vertical ring per column, dense .cs STG.128 at (c*16+p*4).

#define HH 256
#define WW 256
#define CC 8
#define ROWF (WW * CC)       // floats per image row
#define TCOLS 35             // staged w-columns (w0-1 .. w0+33)
#define TPAD 36              // padded stride (bank-conflict-free)
#define NT 11                // staged rows (h0-1 .. h0+9)

__device__ __forceinline__ void cheb4(float x0, float x1, float x2, float x3,
                                      float& y0, float& y1, float& y2, float& y3) {
    const float K3 = 1.0f / 3.0f;
    const float K6 = 1.0f / 6.0f;
    float s0 = x0 + x3, s1 = x1 + x2;
    float d0 = x0 - x3, d1 = x1 - x2;
    y0 = fmaf(s1, K3, s0 * K6);
    y1 = (d0 + d1) * K3;
    y2 = (s0 - s1) * K3;
    y3 = fmaf(d1, -2.0f, d0) * K3;
}

__global__ __launch_bounds__(256, 4)
void cheb_kernel(const float* __restrict__ x, float* __restrict__ out) {
    __shared__ __align__(16) float tile[NT * CC * TPAD];  // [t][c][wcol], 12672B

    int bx = blockIdx.x;
    int wt = bx & 7;            // 8 w-tiles of 32
    int hs = (bx >> 3) & 31;    // 32 h-strips of 8
    int b  = bx >> 8;
    int w0 = wt * 32;
    int h0 = hs * 8;

    const float* src = x + (size_t)b * HH * ROWF / CC * CC;  // b*H*W*C
    // (simplify): base of batch b
    src = x + (size_t)b * HH * WW * CC;

    // ---- staging: 3080 floats, coalesced LDG, transposed conflict-free STS ----
    for (int e = threadIdx.x; e < NT * TCOLS * CC; e += 256) {
        int c    = e & 7;
        int tw   = e >> 3;           // t*35 + wcol
        int t    = tw / TCOLS;
        int wcol = tw - t * TCOLS;
        int r  = min(max(h0 - 1 + t, 0), HH - 1);
        int wc = w0 - 1 + wcol;
        float v = (wc >= 0 && wc < WW)
                    ? src[(size_t)r * ROWF + wc * CC + c] : 0.0f;
        tile[t * (CC * TPAD) + c * TPAD + wcol] = v;
    }
    __syncthreads();

    // ---- consume ----
    int lane = threadIdx.x & 31;
    int wid  = threadIdx.x >> 5;
    int p  = lane >> 3;          // output row index of T
    int c  = lane & 7;           // channel
    int wl = wid * 4;            // first of this warp's 4 pixel columns

    // lane's horizontal Chebyshev row T[p,:]
    const float K3 = 1.0f / 3.0f, K6 = 1.0f / 6.0f, K23 = 2.0f / 3.0f;
    float t0 = (p == 0) ? K6 : K3;
    float t1 = (p <= 1) ? K3 : (p == 2 ? -K3 : -K23);
    float t2 = (p == 0) ? K3 : (p == 3 ? K23 : -K3);
    float t3 = (p == 0) ? K6 : (p == 2 ? K3 : -K3);

    float ring[4][4];
    float* outbase = out + ((size_t)(b * HH + h0) * WW + (w0 + wl)) * 128
                         + (c * 16 + p * 4);

    #pragma unroll
    for (int t = 0; t < NT; t++) {
        const float4* tp =
            (const float4*)&tile[t * (CC * TPAD) + c * TPAD + wl];
        float4 A = tp[0];
        float4 B = tp[1];

        int r = h0 - 1 + t;
        bool rv = (r >= 0) && (r < HH);

        // horizontal dot for the 4 pixel columns (tap windows slide by 1)
        float h0v = fmaf(t0, A.x, fmaf(t1, A.y, fmaf(t2, A.z, t3 * A.w)));
        float h1v = fmaf(t0, A.y, fmaf(t1, A.z, fmaf(t2, A.w, t3 * B.x)));
        float h2v = fmaf(t0, A.z, fmaf(t1, A.w, fmaf(t2, B.x, t3 * B.y)));
        float h3v = fmaf(t0, A.w, fmaf(t1, B.x, fmaf(t2, B.y, t3 * B.z)));
        if (!rv) { h0v = 0.0f; h1v = 0.0f; h2v = 0.0f; h3v = 0.0f; }

        ring[0][t & 3] = h0v;
        ring[1][t & 3] = h1v;
        ring[2][t & 3] = h2v;
        ring[3][t & 3] = h3v;

        if (t >= 3) {
            int s = t - 3;   // output row within strip
            float* orow = outbase + (size_t)s * (WW * 128);
            #pragma unroll
            for (int q = 0; q < 4; q++) {
                float4 o;
                cheb4(ring[q][(t - 3) & 3], ring[q][(t - 2) & 3],
                      ring[q][(t - 1) & 3], ring[q][t & 3],
                      o.x, o.y, o.z, o.w);
                __stcs((float4*)(orow + q * 128), o);
            }
        }
    }
}

extern "C" void kernel_launch(void* const* d_in, const int* in_sizes, int n_in,
                              void* d_out, int out_size) {
    const float* x = (const float*)d_in[0];
    float* out = (float*)d_out;
    // 8 b * 32 hs * 8 wt = 2048 blocks of 256 threads
    cheb_kernel<<<2048, 256>>>(x, out);
}

// round 13
// speedup vs baseline: 1.0013x; 1.0013x over previous
#include <cuda_runtime.h>
#include <cstddef>

// ChebychevTransform: x[8,256,256,8] f32 -> out[8,256,256,128] f32
// out[b,h,w, c*16 + p*4 + k] = sum_{i,j} T[p,j]*T[k,i]*x[b,h+i-1,w+j-1,c]
// (zero pad: 1 before / 2 after, TF SAME n=4)
// T = [[1/6,1/3,1/3,1/6],[1/3,1/3,-1/3,-1/3],[1/3,-1/3,-1/3,1/3],[1/3,-2/3,2/3,-1/3]]
//
// Block = 256 threads = one (b, 8-row strip, 32 w-columns).
// Stage:   input halo tile (11 rows x 35 cols x 8 ch) into smem, transposed to
//          [t][c][wcol] with wcol stride padded to 36 -> conflict-free STS/LDS,
//          16B-aligned float4 reads. W-padding zeroed at staging time.
// Consume: warp = 4 adjacent columns (wl = wid*4); lane = (p=lane>>3, c=lane&7).
//          Per row t: two LDS.128 fetch words wl..wl+7 of (t,c); the 4 pixels'
//          tap windows are register slices of (A,B). 4-FMA dot with T[p,:],
//          vertical ring per column, dense .cs STG.128 at (c*16+p*4).

#define HH 256
#define WW 256
#define CC 8
#define ROWF (WW * CC)       // floats per image row
#define TCOLS 35             // staged w-columns (w0-1 .. w0+33)
#define TPAD 36              // padded stride (bank-conflict-free)
#define NT 11                // staged rows (h0-1 .. h0+9)

__device__ __forceinline__ void cheb4(float x0, float x1, float x2, float x3,
                                      float& y0, float& y1, float& y2, float& y3) {
    const float K3 = 1.0f / 3.0f;
    const float K6 = 1.0f / 6.0f;
    float s0 = x0 + x3, s1 = x1 + x2;
    float d0 = x0 - x3, d1 = x1 - x2;
    y0 = fmaf(s1, K3, s0 * K6);
    y1 = (d0 + d1) * K3;
    y2 = (s0 - s1) * K3;
    y3 = fmaf(d1, -2.0f, d0) * K3;
}

__global__ __launch_bounds__(256, 4)
void cheb_kernel(const float* __restrict__ x, float* __restrict__ out) {
    __shared__ __align__(16) float tile[NT * CC * TPAD];  // [t][c][wcol], 12672B

    int bx = blockIdx.x;
    int wt = bx & 7;            // 8 w-tiles of 32
    int hs = (bx >> 3) & 31;    // 32 h-strips of 8
    int b  = bx >> 8;
    int w0 = wt * 32;
    int h0 = hs * 8;

    const float* src = x + (size_t)b * HH * ROWF / CC * CC;  // b*H*W*C
    // (simplify): base of batch b
    src = x + (size_t)b * HH * WW * CC;

    // ---- staging: 3080 floats, coalesced LDG, transposed conflict-free STS ----
    for (int e = threadIdx.x; e < NT * TCOLS * CC; e += 256) {
        int c    = e & 7;
        int tw   = e >> 3;           // t*35 + wcol
        int t    = tw / TCOLS;
        int wcol = tw - t * TCOLS;
        int r  = min(max(h0 - 1 + t, 0), HH - 1);
        int wc = w0 - 1 + wcol;
        float v = (wc >= 0 && wc < WW)
                    ? src[(size_t)r * ROWF + wc * CC + c] : 0.0f;
        tile[t * (CC * TPAD) + c * TPAD + wcol] = v;
    }
    __syncthreads();

    // ---- consume ----
    int lane = threadIdx.x & 31;
    int wid  = threadIdx.x >> 5;
    int p  = lane >> 3;          // output row index of T
    int c  = lane & 7;           // channel
    int wl = wid * 4;            // first of this warp's 4 pixel columns

    // lane's horizontal Chebyshev row T[p,:]
    const float K3 = 1.0f / 3.0f, K6 = 1.0f / 6.0f, K23 = 2.0f / 3.0f;
    float t0 = (p == 0) ? K6 : K3;
    float t1 = (p <= 1) ? K3 : (p == 2 ? -K3 : -K23);
    float t2 = (p == 0) ? K3 : (p == 3 ? K23 : -K3);
    float t3 = (p == 0) ? K6 : (p == 2 ? K3 : -K3);

    float ring[4][4];
    float* outbase = out + ((size_t)(b * HH + h0) * WW + (w0 + wl)) * 128
                         + (c * 16 + p * 4);

    #pragma unroll
    for (int t = 0; t < NT; t++) {
        const float4* tp =
            (const float4*)&tile[t * (CC * TPAD) + c * TPAD + wl];
        float4 A = tp[0];
        float4 B = tp[1];

        int r = h0 - 1 + t;
        bool rv = (r >= 0) && (r < HH);

        // horizontal dot for the 4 pixel columns (tap windows slide by 1)
        float h0v = fmaf(t0, A.x, fmaf(t1, A.y, fmaf(t2, A.z, t3 * A.w)));
        float h1v = fmaf(t0, A.y, fmaf(t1, A.z, fmaf(t2, A.w, t3 * B.x)));
        float h2v = fmaf(t0, A.z, fmaf(t1, A.w, fmaf(t2, B.x, t3 * B.y)));
        float h3v = fmaf(t0, A.w, fmaf(t1, B.x, fmaf(t2, B.y, t3 * B.z)));
        if (!rv) { h0v = 0.0f; h1v = 0.0f; h2v = 0.0f; h3v = 0.0f; }

        ring[0][t & 3] = h0v;
        ring[1][t & 3] = h1v;
        ring[2][t & 3] = h2v;
        ring[3][t & 3] = h3v;

        if (t >= 3) {
            int s = t - 3;   // output row within strip
            float* orow = outbase + (size_t)s * (WW * 128);
            #pragma unroll
            for (int q = 0; q < 4; q++) {
                float4 o;
                cheb4(ring[q][(t - 3) & 3], ring[q][(t - 2) & 3],
                      ring[q][(t - 1) & 3], ring[q][t & 3],
                      o.x, o.y, o.z, o.w);
                __stcs((float4*)(orow + q * 128), o);
            }
        }
    }
}

extern "C" void kernel_launch(void* const* d_in, const int* in_sizes, int n_in,
                              void* d_out, int out_size) {
    const float* x = (const float*)d_in[0];
    float* out = (float*)d_out;
    // 8 b * 32 hs * 8 wt = 2048 blocks of 256 threads
    cheb_kernel<<<2048, 256>>>(x, out);
}

// round 14
// speedup vs baseline: 1.0403x; 1.0390x over previous
#include <cuda_runtime.h>
#include <cstddef>

// ChebychevTransform: x[8,256,256,8] f32 -> out[8,256,256,128] f32
// out[b,h,w, c*16 + p*4 + k] = sum_{i,j} T[p,j]*T[k,i]*x[b,h+i-1,w+j-1,c]
// (zero pad: 1 before / 2 after, TF SAME n=4)
// T = [[1/6,1/3,1/3,1/6],[1/3,1/3,-1/3,-1/3],[1/3,-1/3,-1/3,1/3],[1/3,-2/3,2/3,-1/3]]
//
// Block = 256 thr = (b, 32-col w-tile, 32-row h-group), looping 4 strips of 8
// rows with DOUBLE-BUFFERED smem staging:
//   tile[2][11 rows][8 ch][36-padded cols]  (conflict-free STS/LDS, 16B aligned)
// Pipeline per strip: LDGs for strip s+1 issue BEFORE consuming strip s, so
// global latency is hidden under consume's LDS/FMA/STG stream.
// Consume: warp = 4 adjacent pixel columns, lane = (p=lane>>3, c=lane&7);
// 2 broadcast LDS.128 per row feed 4 sliding 4-tap windows; vertical register
// ring; dense .cs STG.128 at (c*16 + bitrev-free p*4).

#define HH 256
#define WW 256
#define CC 8
#define ROWF (WW * CC)
#define SS 8
#define NS 4                    // strips per block
#define NT 11                   // staged rows per strip
#define TCOLS 35                // staged w-columns (w0-1 .. w0+33)
#define TPAD 36
#define TSTRIDE (CC * TPAD)     // floats per staged row = 288
#define NELEM (NT * TCOLS * CC) // 3080 staged elements
#define NK 13                   // staging slots per thread (ceil 3080/256)

__device__ __forceinline__ void cheb4(float x0, float x1, float x2, float x3,
                                      float& y0, float& y1, float& y2, float& y3) {
    const float K3 = 1.0f / 3.0f;
    const float K6 = 1.0f / 6.0f;
    float s0 = x0 + x3, s1 = x1 + x2;
    float d0 = x0 - x3, d1 = x1 - x2;
    y0 = fmaf(s1, K3, s0 * K6);
    y1 = (d0 + d1) * K3;
    y2 = (s0 - s1) * K3;
    y3 = fmaf(d1, -2.0f, d0) * K3;
}

__global__ __launch_bounds__(256)
void cheb_kernel(const float* __restrict__ x, float* __restrict__ out) {
    __shared__ __align__(16) float tile[2][NT * TSTRIDE];   // 2 x 12672 B

    int bx = blockIdx.x;
    int wt = bx & 7;             // 8 w-tiles of 32
    int hg = (bx >> 3) & 7;      // 8 h-groups of 32 rows
    int b  = bx >> 6;
    int w0 = wt * 32;
    int hbase = hg * (SS * NS);

    int tid = threadIdx.x;
    const float* src = x + (size_t)b * HH * ROWF;

    // ---- staging load: gather strip s's halo into pf[] (13 LDGs, high MLP) ----
    float pf[NK];
    auto stage_load = [&](int h0) {
        #pragma unroll
        for (int k = 0; k < NK; k++) {
            int e = tid + k * 256;
            if (e < NELEM) {
                int c    = e & 7;
                int tw   = e >> 3;
                int t    = tw / TCOLS;
                int wcol = tw - t * TCOLS;
                int r  = min(max(h0 - 1 + t, 0), HH - 1);
                int wc = w0 - 1 + wcol;
                pf[k] = (wc >= 0 && wc < WW)
                          ? src[(size_t)r * ROWF + wc * CC + c] : 0.0f;
            }
        }
    };
    auto stage_store = [&](float* buf) {
        #pragma unroll
        for (int k = 0; k < NK; k++) {
            int e = tid + k * 256;
            if (e < NELEM) {
                int c    = e & 7;
                int tw   = e >> 3;
                int t    = tw / TCOLS;
                int wcol = tw - t * TCOLS;
                buf[t * TSTRIDE + c * TPAD + wcol] = pf[k];
            }
        }
    };

    // ---- consume lane mapping ----
    int lane = tid & 31;
    int wid  = tid >> 5;
    int p  = lane >> 3;
    int c  = lane & 7;
    int wl = wid * 4;

    const float K3 = 1.0f / 3.0f, K6 = 1.0f / 6.0f, K23 = 2.0f / 3.0f;
    float t0c = (p == 0) ? K6 : K3;
    float t1c = (p <= 1) ? K3 : (p == 2 ? -K3 : -K23);
    float t2c = (p == 0) ? K3 : (p == 3 ? K23 : -K3);
    float t3c = (p == 0) ? K6 : (p == 2 ? K3 : -K3);

    // ---- pipelined strip loop ----
    stage_load(hbase);
    stage_store(tile[0]);
    __syncthreads();

    for (int s = 0; s < NS; s++) {
        int h0 = hbase + s * SS;
        if (s + 1 < NS) stage_load(h0 + SS);     // LDGs in flight during consume

        const float* buf = tile[s & 1];
        float ring[4][4];
        float* outbase = out + ((size_t)(b * HH + h0) * WW + (w0 + wl)) * 128
                             + (c * 16 + p * 4);

        #pragma unroll
        for (int t = 0; t < NT; t++) {
            const float4* tp = (const float4*)&buf[t * TSTRIDE + c * TPAD + wl];
            float4 A = tp[0];
            float4 B = tp[1];

            int r = h0 - 1 + t;
            bool rv = (r >= 0) && (r < HH);

            float h0v = fmaf(t0c, A.x, fmaf(t1c, A.y, fmaf(t2c, A.z, t3c * A.w)));
            float h1v = fmaf(t0c, A.y, fmaf(t1c, A.z, fmaf(t2c, A.w, t3c * B.x)));
            float h2v = fmaf(t0c, A.z, fmaf(t1c, A.w, fmaf(t2c, B.x, t3c * B.y)));
            float h3v = fmaf(t0c, A.w, fmaf(t1c, B.x, fmaf(t2c, B.y, t3c * B.z)));
            if (!rv) { h0v = 0.0f; h1v = 0.0f; h2v = 0.0f; h3v = 0.0f; }

            ring[0][t & 3] = h0v;
            ring[1][t & 3] = h1v;
            ring[2][t & 3] = h2v;
            ring[3][t & 3] = h3v;

            if (t >= 3) {
                float* orow = outbase + (size_t)(t - 3) * (WW * 128);
                #pragma unroll
                for (int q = 0; q < 4; q++) {
                    float4 o;
                    cheb4(ring[q][(t - 3) & 3], ring[q][(t - 2) & 3],
                          ring[q][(t - 1) & 3], ring[q][t & 3],
                          o.x, o.y, o.z, o.w);
                    __stcs((float4*)(orow + q * 128), o);
                }
            }
        }

        if (s + 1 < NS) {
            __syncthreads();                     // all readers of tile[s&1] done
            stage_store(tile[(s + 1) & 1]);
            __syncthreads();                     // buffer ready for consume
        }
    }
}

extern "C" void kernel_launch(void* const* d_in, const int* in_sizes, int n_in,
                              void* d_out, int out_size) {
    const float* x = (const float*)d_in[0];
    float* out = (float*)d_out;
    // 8 b * 8 hg * 8 wt = 512 blocks of 256 threads (~single residency wave)
    cheb_kernel<<<512, 256>>>(x, out);
}